// round 3
// baseline (speedup 1.0000x reference)
#include <cuda_runtime.h>
#include <math.h>

#define B_ 256
#define S_ 120
#define T_ 24
#define D_ 216
#define H_ 1024
#define G_ 4096           // 4*H
#define KTOT (H_ + D_)    // 1240

// ---------------- scratch (device globals; no allocations allowed) ----------
__device__ float g_h[2][B_ * H_];     // ping-pong hidden state
__device__ float g_c[B_ * H_];        // cell state (in-place update)
__device__ float g_bias[G_];          // b_ih + b_hh
__device__ float g_xdec[B_ * D_];     // decoder feedback input
__device__ float g_proj[8][B_ * D_];  // split-K partials for output projection

__device__ __forceinline__ float sigf(float v) { return 1.f / (1.f + expf(-v)); }

// ---------------- init ------------------------------------------------------
__global__ void init_kernel(const float* __restrict__ b_ih,
                            const float* __restrict__ b_hh) {
    int idx = blockIdx.x * blockDim.x + threadIdx.x;
    if (idx < B_ * H_) { g_h[0][idx] = 0.f; g_c[idx] = 0.f; }
    if (idx < G_) g_bias[idx] = b_ih[idx] + b_hh[idx];
}

// ---------------- fused gates GEMM + LSTM cell -------------------------------
// One kernel per time step. BM=64 (batch), BN=64 (= 16 hidden units x 4 gates,
// interleaved), BK=8, 256 threads, 4x4 microtile. Grid (64, 4) = 256 blocks.
// Column interleave: local col r -> weight row (r&3)*1024 + j0 + (r>>2), so a
// thread's 4 columns are gates (i,f,g,o) of one hidden unit j -> fused epilogue.
__global__ void __launch_bounds__(256, 2)
lstm_step(int hbuf, const float* __restrict__ xsrc, int xstride, int use_xdec,
          const float* __restrict__ Whh, const float* __restrict__ Wih)
{
    __shared__ float As[2][8][68];    // [buf][k][m], padded
    __shared__ float Bs[2][8][68];    // [buf][k][n_local], padded

    const float* __restrict__ h = g_h[hbuf];
    const float* __restrict__ x = use_xdec ? g_xdec : xsrc;
    if (use_xdec) xstride = D_;

    const int tid = threadIdx.x;
    const int j0  = blockIdx.x * 16;     // hidden-unit group
    const int m0  = blockIdx.y * 64;     // batch group

    // loader mapping: 64 rows x 8 k per tile, 2 floats/thread (float2 along k)
    const int lm = tid >> 2;             // 0..63
    const int lk = (tid & 3) * 2;        // 0,2,4,6

    // B global row for local col lm (interleaved gate layout)
    const int grow = (lm & 3) * H_ + j0 + (lm >> 2);

    // compute mapping: 4x4 microtile
    const int ty = tid >> 4;             // 0..15 -> rows ty*4..ty*4+3
    const int tx = tid & 15;             // 0..15 -> hidden unit j0+tx (4 gates)

    float acc[4][4];
    #pragma unroll
    for (int i = 0; i < 4; i++)
        #pragma unroll
        for (int q = 0; q < 4; q++) acc[i][q] = 0.f;

    float2 aR, bR;

    // prologue: chunk 0 (always in h / W_hh region)
    aR = *(const float2*)&h[(m0 + lm) * H_ + lk];
    bR = *(const float2*)&Whh[grow * H_ + lk];
    As[0][lk + 0][lm] = aR.x; As[0][lk + 1][lm] = aR.y;
    Bs[0][lk + 0][lm] = bR.x; Bs[0][lk + 1][lm] = bR.y;
    __syncthreads();

    const int NC = KTOT / 8;  // 155; [0,128) are h/W_hh, [128,155) are x/W_ih
    for (int ch = 1; ch <= NC; ch++) {
        if (ch < NC) {
            int k0 = ch * 8;
            if (k0 < H_) {
                aR = *(const float2*)&h[(m0 + lm) * H_ + k0 + lk];
                bR = *(const float2*)&Whh[grow * H_ + k0 + lk];
            } else {
                int kk = k0 - H_;
                aR = *(const float2*)&x[(m0 + lm) * xstride + kk + lk];
                bR = *(const float2*)&Wih[grow * D_ + kk + lk];
            }
        }
        int cb = (ch - 1) & 1;
        #pragma unroll
        for (int k = 0; k < 8; k++) {
            float4 a = *(const float4*)&As[cb][k][ty * 4];
            float4 b = *(const float4*)&Bs[cb][k][tx * 4];
            float av[4] = {a.x, a.y, a.z, a.w};
            float bv[4] = {b.x, b.y, b.z, b.w};
            #pragma unroll
            for (int i = 0; i < 4; i++)
                #pragma unroll
                for (int q = 0; q < 4; q++)
                    acc[i][q] += av[i] * bv[q];
        }
        if (ch < NC) {
            int sb = ch & 1;
            As[sb][lk + 0][lm] = aR.x; As[sb][lk + 1][lm] = aR.y;
            Bs[sb][lk + 0][lm] = bR.x; Bs[sb][lk + 1][lm] = bR.y;
        }
        __syncthreads();
    }

    // fused LSTM epilogue: thread owns gates (i,f,g,o) of unit j for 4 rows
    const int j = j0 + tx;
    const float bi = g_bias[j];
    const float bf = g_bias[H_ + j];
    const float bg = g_bias[2 * H_ + j];
    const float bo = g_bias[3 * H_ + j];
    float* __restrict__ hout = g_h[1 - hbuf];
    #pragma unroll
    for (int i = 0; i < 4; i++) {
        int idx = (m0 + ty * 4 + i) * H_ + j;
        float c = sigf(acc[i][1] + bf) * g_c[idx]
                + sigf(acc[i][0] + bi) * tanhf(acc[i][2] + bg);
        g_c[idx]  = c;
        hout[idx] = sigf(acc[i][3] + bo) * tanhf(c);
    }
}

// ---------------- projection GEMM (split-K) ---------------------------------
__global__ void __launch_bounds__(256, 2)
proj_gemm(int hbuf, const float* __restrict__ Wout)
{
    __shared__ float As[2][8][132];
    __shared__ float Bs[2][8][68];

    const float* __restrict__ h = g_h[hbuf];
    int tid = threadIdx.x;
    int n0 = blockIdx.x * 64;
    int m0 = blockIdx.y * 128;
    int ks = blockIdx.z;
    int kbase = ks * 128;

    int lmA = tid >> 1;
    int lkA = (tid & 1) * 4;
    int lmB = tid >> 2;
    int lkB = (tid & 3) * 2;
    int ty = tid >> 4;
    int tx = tid & 15;

    float acc[8][4];
    #pragma unroll
    for (int i = 0; i < 8; i++)
        #pragma unroll
        for (int j = 0; j < 4; j++) acc[i][j] = 0.f;

    float4 aR;
    float2 bR;
    int dB = n0 + lmB;

    aR = *(const float4*)&h[(m0 + lmA) * H_ + kbase + lkA];
    bR = (dB < D_) ? *(const float2*)&Wout[dB * H_ + kbase + lkB]
                   : make_float2(0.f, 0.f);
    As[0][lkA + 0][lmA] = aR.x; As[0][lkA + 1][lmA] = aR.y;
    As[0][lkA + 2][lmA] = aR.z; As[0][lkA + 3][lmA] = aR.w;
    Bs[0][lkB + 0][lmB] = bR.x; Bs[0][lkB + 1][lmB] = bR.y;
    __syncthreads();

    const int NC = 128 / 8;
    for (int ch = 1; ch <= NC; ch++) {
        if (ch < NC) {
            int k0 = kbase + ch * 8;
            aR = *(const float4*)&h[(m0 + lmA) * H_ + k0 + lkA];
            bR = (dB < D_) ? *(const float2*)&Wout[dB * H_ + k0 + lkB]
                           : make_float2(0.f, 0.f);
        }
        int cbuf = (ch - 1) & 1;
        #pragma unroll
        for (int k = 0; k < 8; k++) {
            float4 a0 = *(const float4*)&As[cbuf][k][ty * 8];
            float4 a1 = *(const float4*)&As[cbuf][k][ty * 8 + 4];
            float4 b  = *(const float4*)&Bs[cbuf][k][tx * 4];
            float av[8] = {a0.x, a0.y, a0.z, a0.w, a1.x, a1.y, a1.z, a1.w};
            float bv[4] = {b.x, b.y, b.z, b.w};
            #pragma unroll
            for (int i = 0; i < 8; i++)
                #pragma unroll
                for (int j = 0; j < 4; j++)
                    acc[i][j] += av[i] * bv[j];
        }
        if (ch < NC) {
            int sbuf = ch & 1;
            As[sbuf][lkA + 0][lmA] = aR.x; As[sbuf][lkA + 1][lmA] = aR.y;
            As[sbuf][lkA + 2][lmA] = aR.z; As[sbuf][lkA + 3][lmA] = aR.w;
            Bs[sbuf][lkB + 0][lmB] = bR.x; Bs[sbuf][lkB + 1][lmB] = bR.y;
        }
        __syncthreads();
    }

    #pragma unroll
    for (int i = 0; i < 8; i++)
        #pragma unroll
        for (int j = 0; j < 4; j++) {
            int col = n0 + tx * 4 + j;
            if (col < D_)
                g_proj[ks][(m0 + ty * 8 + i) * D_ + col] = acc[i][j];
        }
}

// ---------------- projection reduce + output write ---------------------------
__global__ void proj_reduce(const float* __restrict__ b_out,
                            float* __restrict__ out, int t)
{
    int idx = blockIdx.x * blockDim.x + threadIdx.x;
    if (idx >= B_ * D_) return;
    int b = idx / D_;
    int d = idx - b * D_;
    float v = b_out[d];
    #pragma unroll
    for (int s = 0; s < 8; s++) v += g_proj[s][idx];
    out[b * (T_ * D_) + t * D_ + d] = v;  // [B, T, D]
    g_xdec[idx] = v;                      // decoder feedback
}

// ---------------- host orchestration ----------------------------------------
extern "C" void kernel_launch(void* const* d_in, const int* in_sizes, int n_in,
                              void* d_out, int out_size)
{
    (void)in_sizes; (void)n_in; (void)out_size;
    const float* src   = (const float*)d_in[0];
    // d_in[1] = tgt: unused (eval-mode autoregressive decoder)
    const float* W_ih  = (const float*)d_in[2];
    const float* W_hh  = (const float*)d_in[3];
    const float* b_ih  = (const float*)d_in[4];
    const float* b_hh  = (const float*)d_in[5];
    const float* W_out = (const float*)d_in[6];
    const float* b_out = (const float*)d_in[7];
    float* out = (float*)d_out;

    init_kernel<<<(B_ * H_ + 255) / 256, 256>>>(b_ih, b_hh);

    dim3 gg(H_ / 16, B_ / 64);    // (64, 4) = 256 blocks
    dim3 pg(4, B_ / 128, 8);      // (4, 2, 8) = 64 blocks
    int cur = 0;

    // Encoder: teacher-forced over src
    for (int t = 0; t < S_; t++) {
        lstm_step<<<gg, 256>>>(cur, src + t * D_, S_ * D_, 0, W_hh, W_ih);
        cur ^= 1;
    }

    // Decoder: autoregressive from last src frame
    for (int t = 0; t < T_; t++) {
        if (t == 0)
            lstm_step<<<gg, 256>>>(cur, src + (S_ - 1) * D_, S_ * D_, 0, W_hh, W_ih);
        else
            lstm_step<<<gg, 256>>>(cur, src, 0, 1, W_hh, W_ih);
        cur ^= 1;
        proj_gemm<<<pg, 256>>>(cur, W_out);
        proj_reduce<<<(B_ * D_ + 255) / 256, 256>>>(b_out, out, t);
    }
}

// round 5
// speedup vs baseline: 2.3027x; 2.3027x over previous
#include <cuda_runtime.h>
#include <cuda_bf16.h>
#include <math.h>
#include <stdint.h>

#define B_ 256
#define S_ 120
#define T_ 24
#define D_ 216
#define H_ 1024
#define G_ 4096           // 4*H
#define KP 1280           // padded K (1024 h + 216 x + 40 zero)
#define XP 256            // padded x row width
#define BK 32
#define NCH (KP / BK)     // 40
#define NSTAGE 3
// per-stage smem: A 2 splits x 128 rows x 80B + B 2 splits x 64 rows x 80B
#define A_PITCH 80
#define ASPLIT_BYTES (128 * A_PITCH)   // 10240
#define BSPLIT_BYTES (64 * A_PITCH)    // 5120
#define STAGE_BYTES (2 * ASPLIT_BYTES + 2 * BSPLIT_BYTES)  // 30720
#define SMEM_DYN (NSTAGE * STAGE_BYTES)                    // 92160

// ---------------- device globals (no allocations allowed) --------------------
__device__ __align__(16) __nv_bfloat16 g_Wp_hi[G_ * KP];      // permuted, split
__device__ __align__(16) __nv_bfloat16 g_Wp_lo[G_ * KP];
__device__ __align__(16) __nv_bfloat16 g_xe_hi[S_ * B_ * XP]; // encoder x splits
__device__ __align__(16) __nv_bfloat16 g_xe_lo[S_ * B_ * XP];
__device__ __align__(16) __nv_bfloat16 g_xd_hi[B_ * XP];      // decoder x splits
__device__ __align__(16) __nv_bfloat16 g_xd_lo[B_ * XP];
__device__ __align__(16) __nv_bfloat16 g_ah_hi[2][B_ * H_];   // h splits, ping-pong
__device__ __align__(16) __nv_bfloat16 g_ah_lo[2][B_ * H_];
__device__ float g_hf[B_ * H_];       // fp32 h (projection input)
__device__ float g_c[B_ * H_];        // cell state
__device__ float g_bp[G_];            // permuted combined bias
__device__ float g_proj[8][B_ * D_];  // split-K projection partials

__device__ __forceinline__ float sigf(float v) { return 1.f / (1.f + expf(-v)); }

// ---------------- PTX helpers (baseline sm_80+ only) -------------------------
__device__ __forceinline__ uint32_t smem_u32(const void* p) {
    uint32_t a;
    asm("{ .reg .u64 t; cvta.to.shared.u64 t, %1; cvt.u32.u64 %0, t; }"
        : "=r"(a) : "l"(p));
    return a;
}
#define CP_ASYNC16(dst, src) \
    asm volatile("cp.async.ca.shared.global [%0], [%1], 16;" :: "r"(dst), "l"(src))
#define CP_COMMIT() asm volatile("cp.async.commit_group;" ::: "memory")
#define CP_WAIT1()  asm volatile("cp.async.wait_group 1;" ::: "memory")

#define LDSM_X4(r0, r1, r2, r3, a) \
    asm volatile("ldmatrix.sync.aligned.m8n8.x4.shared.b16 {%0,%1,%2,%3}, [%4];" \
                 : "=r"(r0), "=r"(r1), "=r"(r2), "=r"(r3) : "r"(a))

#define MMA16816(d, a, b) \
    asm volatile("mma.sync.aligned.m16n8k16.row.col.f32.bf16.bf16.f32 " \
                 "{%0,%1,%2,%3},{%4,%5,%6,%7},{%8,%9},{%0,%1,%2,%3};" \
                 : "+f"((d)[0]), "+f"((d)[1]), "+f"((d)[2]), "+f"((d)[3]) \
                 : "r"((a)[0]), "r"((a)[1]), "r"((a)[2]), "r"((a)[3]), \
                   "r"((b)[0]), "r"((b)[1]))

// ---------------- prep kernels ----------------------------------------------
// Permutation: permuted col p -> bn=p>>6, c=p&63, u=c>>2, q=c&3, unit j=bn*16+u,
// original weight row = q*H_ + j. A CTA's 64 cols = 16 units x 4 gates.
__global__ void prep_weights(const float* __restrict__ W_ih,
                             const float* __restrict__ W_hh,
                             const float* __restrict__ b_ih,
                             const float* __restrict__ b_hh)
{
    int idx = blockIdx.x * blockDim.x + threadIdx.x;  // G_*KP threads
    int p = idx / KP, k = idx - p * KP;
    int bn = p >> 6, c = p & 63, u = c >> 2, q = c & 3;
    int j = bn * 16 + u;
    int orig = q * H_ + j;
    float w = 0.f;
    if (k < H_) w = W_hh[orig * H_ + k];
    else if (k < H_ + D_) w = W_ih[orig * D_ + (k - H_)];
    __nv_bfloat16 hi = __float2bfloat16(w);
    g_Wp_hi[idx] = hi;
    g_Wp_lo[idx] = __float2bfloat16(w - __bfloat162float(hi));
    if (k == 0) g_bp[p] = b_ih[orig] + b_hh[orig];
}

__global__ void prep_xe(const float* __restrict__ src)
{
    int idx = blockIdx.x * blockDim.x + threadIdx.x;  // S_*B_*XP threads
    int t = idx >> 16;            // B_*XP = 65536
    int r = idx & 65535;
    int b = r >> 8, kk = r & 255;
    float v = (kk < D_) ? src[(b * S_ + t) * D_ + kk] : 0.f;
    __nv_bfloat16 hi = __float2bfloat16(v);
    g_xe_hi[idx] = hi;
    g_xe_lo[idx] = __float2bfloat16(v - __bfloat162float(hi));
}

__global__ void init_state()
{
    int idx = blockIdx.x * blockDim.x + threadIdx.x;
    if (idx < B_ * H_) {
        g_c[idx] = 0.f;
        g_ah_hi[0][idx] = __float2bfloat16(0.f);
        g_ah_lo[0][idx] = __float2bfloat16(0.f);
    }
    if (idx < B_ * XP) {
        g_xd_hi[idx] = __float2bfloat16(0.f);
        g_xd_lo[idx] = __float2bfloat16(0.f);
    }
}

// ---------------- fused LSTM step: HMMA split-bf16 GEMM + cell ---------------
// grid (64, 2): blockIdx.x = N tile (64 permuted cols = 16 units),
//               blockIdx.y = M tile (128 batch rows). 256 threads = 8 warps 4x2.
__global__ void __launch_bounds__(256, 1)
lstm_step_mma(int hbuf, int xsel, int xoff)
{
    extern __shared__ __align__(128) char smem[];
    const uint32_t sb = smem_u32(smem);
    const int tid = threadIdx.x;
    const int wid = tid >> 5;
    const int lane = tid & 31;
    const int bn = blockIdx.x;
    const int m0 = blockIdx.y << 7;
    const int n0 = bn << 6;

    const __nv_bfloat16* __restrict__ ah_hi = g_ah_hi[hbuf];
    const __nv_bfloat16* __restrict__ ah_lo = g_ah_lo[hbuf];
    const __nv_bfloat16* __restrict__ x_hi = xsel ? g_xd_hi : (g_xe_hi + xoff);
    const __nv_bfloat16* __restrict__ x_lo = xsel ? g_xd_lo : (g_xe_lo + xoff);
    const __nv_bfloat16* __restrict__ wp_hi = g_Wp_hi;
    const __nv_bfloat16* __restrict__ wp_lo = g_Wp_lo;

    // stage loader: 1024 A-chunks (16B) + 512 B-chunks per stage, 6 per thread
    auto load_stage = [&](int ch, int slot) {
        uint32_t s = sb + slot * STAGE_BYTES;
        #pragma unroll
        for (int i = 0; i < 4; i++) {
            int idx = i * 256 + tid;
            int row = idx >> 3, rem = idx & 7;
            int split = rem >> 2, c4 = rem & 3;
            const __nv_bfloat16* g;
            if (ch < 32)
                g = (split ? ah_lo : ah_hi) + (size_t)(m0 + row) * H_ + ch * BK + c4 * 8;
            else
                g = (split ? x_lo : x_hi) + (size_t)(m0 + row) * XP + (ch - 32) * BK + c4 * 8;
            CP_ASYNC16(s + split * ASPLIT_BYTES + row * A_PITCH + c4 * 16, g);
        }
        #pragma unroll
        for (int i = 0; i < 2; i++) {
            int idx = i * 256 + tid;
            int row = idx >> 3, rem = idx & 7;
            int split = rem >> 2, c4 = rem & 3;
            const __nv_bfloat16* g =
                (split ? wp_lo : wp_hi) + (size_t)(n0 + row) * KP + ch * BK + c4 * 8;
            CP_ASYNC16(s + 2 * ASPLIT_BYTES + split * BSPLIT_BYTES
                         + row * A_PITCH + c4 * 16, g);
        }
    };

    const int warpM = wid >> 1;   // 0..3 -> rows warpM*32
    const int warpN = wid & 1;    // 0..1 -> cols warpN*32

    float acc[2][4][4];
    #pragma unroll
    for (int i = 0; i < 2; i++)
        #pragma unroll
        for (int j = 0; j < 4; j++)
            #pragma unroll
            for (int q = 0; q < 4; q++) acc[i][j][q] = 0.f;

    // ldmatrix lane-address components (constant per thread)
    const int tsel = lane >> 3;          // tile index 0..3
    // A x4 tiles: t0 m-lo k-lo, t1 m-hi k-lo, t2 m-lo k-hi, t3 m-hi k-hi
    const int aRow = (tsel & 1) * 8 + (lane & 7);
    const int aKof = (tsel >> 1) * 16;   // bytes
    // B x4 tiles: t0 n-lo k-lo, t1 n-lo k-hi, t2 n-hi k-lo, t3 n-hi k-hi
    const int bRow = (tsel >> 1) * 8 + (lane & 7);
    const int bKof = (tsel & 1) * 16;    // bytes

    load_stage(0, 0); CP_COMMIT();
    load_stage(1, 1); CP_COMMIT();

    #pragma unroll 1
    for (int ch = 0; ch < NCH; ch++) {
        CP_WAIT1();
        __syncthreads();
        if (ch + 2 < NCH) load_stage(ch + 2, (ch + 2) % NSTAGE);
        CP_COMMIT();

        uint32_t s = sb + (ch % NSTAGE) * STAGE_BYTES;
        #pragma unroll
        for (int kh = 0; kh < 2; kh++) {
            uint32_t a_hi[2][4], a_lo[2][4];
            #pragma unroll
            for (int mt = 0; mt < 2; mt++) {
                uint32_t ra = s + (warpM * 32 + mt * 16 + aRow) * A_PITCH
                                + kh * 32 + aKof;
                LDSM_X4(a_hi[mt][0], a_hi[mt][1], a_hi[mt][2], a_hi[mt][3], ra);
                LDSM_X4(a_lo[mt][0], a_lo[mt][1], a_lo[mt][2], a_lo[mt][3],
                        ra + ASPLIT_BYTES);
            }
            uint32_t b_hi[4][2], b_lo[4][2];
            #pragma unroll
            for (int gq = 0; gq < 2; gq++) {
                uint32_t rb = s + 2 * ASPLIT_BYTES
                                + (warpN * 32 + gq * 16 + bRow) * A_PITCH
                                + kh * 32 + bKof;
                uint32_t r0, r1, r2, r3;
                LDSM_X4(r0, r1, r2, r3, rb);
                b_hi[gq * 2 + 0][0] = r0; b_hi[gq * 2 + 0][1] = r1;
                b_hi[gq * 2 + 1][0] = r2; b_hi[gq * 2 + 1][1] = r3;
                LDSM_X4(r0, r1, r2, r3, rb + BSPLIT_BYTES);
                b_lo[gq * 2 + 0][0] = r0; b_lo[gq * 2 + 0][1] = r1;
                b_lo[gq * 2 + 1][0] = r2; b_lo[gq * 2 + 1][1] = r3;
            }
            #pragma unroll
            for (int mt = 0; mt < 2; mt++)
                #pragma unroll
                for (int ni = 0; ni < 4; ni++) {
                    MMA16816(acc[mt][ni], a_hi[mt], b_hi[ni]);
                    MMA16816(acc[mt][ni], a_hi[mt], b_lo[ni]);
                    MMA16816(acc[mt][ni], a_lo[mt], b_hi[ni]);
                }
        }
        __syncthreads();
    }

    // ---- epilogue: stage gates through smem, fused LSTM cell ----
    float* gbuf = (float*)smem;           // [128][66] f32 = 33.8KB (reuses stages)
    const int GP = 66;
    #pragma unroll
    for (int mt = 0; mt < 2; mt++)
        #pragma unroll
        for (int ni = 0; ni < 4; ni++) {
            int r0 = warpM * 32 + mt * 16 + (lane >> 2);
            int c0 = warpN * 32 + ni * 8 + 2 * (lane & 3);
            gbuf[r0 * GP + c0]           = acc[mt][ni][0];
            gbuf[r0 * GP + c0 + 1]       = acc[mt][ni][1];
            gbuf[(r0 + 8) * GP + c0]     = acc[mt][ni][2];
            gbuf[(r0 + 8) * GP + c0 + 1] = acc[mt][ni][3];
        }
    __syncthreads();

    {
        const int u = tid & 15;           // local unit 0..15
        const int rg = tid >> 4;          // row group 0..15 (8 rows each)
        const int j = bn * 16 + u;        // global hidden unit
        const float bi = g_bp[n0 + u * 4 + 0];
        const float bf = g_bp[n0 + u * 4 + 1];
        const float bg = g_bp[n0 + u * 4 + 2];
        const float bo = g_bp[n0 + u * 4 + 3];
        __nv_bfloat16* __restrict__ oh = g_ah_hi[1 - hbuf];
        __nv_bfloat16* __restrict__ ol = g_ah_lo[1 - hbuf];
        #pragma unroll
        for (int rr = 0; rr < 8; rr++) {
            int r = rg * 8 + rr;
            const float* gr = &gbuf[r * GP + u * 4];
            float gi = gr[0] + bi;
            float gf = gr[1] + bf;
            float gg = gr[2] + bg;
            float go = gr[3] + bo;
            size_t idx = (size_t)(m0 + r) * H_ + j;
            float cn = sigf(gf) * g_c[idx] + sigf(gi) * tanhf(gg);
            g_c[idx] = cn;
            float hn = sigf(go) * tanhf(cn);
            g_hf[idx] = hn;
            __nv_bfloat16 hh = __float2bfloat16(hn);
            oh[idx] = hh;
            ol[idx] = __float2bfloat16(hn - __bfloat162float(hh));
        }
    }
}

// ---------------- projection GEMM (fp32, split-K=8; reads g_hf) --------------
__global__ void __launch_bounds__(256, 2)
proj_gemm(const float* __restrict__ Wout)
{
    __shared__ float As[2][8][132];
    __shared__ float Bs[2][8][68];

    const float* __restrict__ h = g_hf;
    int tid = threadIdx.x;
    int n0 = blockIdx.x * 64;
    int m0 = blockIdx.y * 128;
    int ks = blockIdx.z;
    int kbase = ks * 128;

    int lmA = tid >> 1, lkA = (tid & 1) * 4;
    int lmB = tid >> 2, lkB = (tid & 3) * 2;
    int ty = tid >> 4, tx = tid & 15;

    float acc[8][4];
    #pragma unroll
    for (int i = 0; i < 8; i++)
        #pragma unroll
        for (int j = 0; j < 4; j++) acc[i][j] = 0.f;

    float4 aR; float2 bR;
    int dB = n0 + lmB;

    aR = *(const float4*)&h[(m0 + lmA) * H_ + kbase + lkA];
    bR = (dB < D_) ? *(const float2*)&Wout[dB * H_ + kbase + lkB] : make_float2(0.f, 0.f);
    As[0][lkA + 0][lmA] = aR.x; As[0][lkA + 1][lmA] = aR.y;
    As[0][lkA + 2][lmA] = aR.z; As[0][lkA + 3][lmA] = aR.w;
    Bs[0][lkB + 0][lmB] = bR.x; Bs[0][lkB + 1][lmB] = bR.y;
    __syncthreads();

    const int NC = 16;
    for (int ch = 1; ch <= NC; ch++) {
        if (ch < NC) {
            int k0 = kbase + ch * 8;
            aR = *(const float4*)&h[(m0 + lmA) * H_ + k0 + lkA];
            bR = (dB < D_) ? *(const float2*)&Wout[dB * H_ + k0 + lkB] : make_float2(0.f, 0.f);
        }
        int cb = (ch - 1) & 1;
        #pragma unroll
        for (int k = 0; k < 8; k++) {
            float4 a0 = *(const float4*)&As[cb][k][ty * 8];
            float4 a1 = *(const float4*)&As[cb][k][ty * 8 + 4];
            float4 bb = *(const float4*)&Bs[cb][k][tx * 4];
            float av[8] = {a0.x, a0.y, a0.z, a0.w, a1.x, a1.y, a1.z, a1.w};
            float bv[4] = {bb.x, bb.y, bb.z, bb.w};
            #pragma unroll
            for (int i = 0; i < 8; i++)
                #pragma unroll
                for (int j = 0; j < 4; j++)
                    acc[i][j] += av[i] * bv[j];
        }
        if (ch < NC) {
            int sbuf = ch & 1;
            As[sbuf][lkA + 0][lmA] = aR.x; As[sbuf][lkA + 1][lmA] = aR.y;
            As[sbuf][lkA + 2][lmA] = aR.z; As[sbuf][lkA + 3][lmA] = aR.w;
            Bs[sbuf][lkB + 0][lmB] = bR.x; Bs[sbuf][lkB + 1][lmB] = bR.y;
        }
        __syncthreads();
    }

    #pragma unroll
    for (int i = 0; i < 8; i++)
        #pragma unroll
        for (int j = 0; j < 4; j++) {
            int col = n0 + tx * 4 + j;
            if (col < D_)
                g_proj[ks][(m0 + ty * 8 + i) * D_ + col] = acc[i][j];
        }
}

// ---------------- projection reduce: output + decoder-feedback split ---------
__global__ void proj_reduce(const float* __restrict__ b_out,
                            float* __restrict__ out, int t)
{
    int idx = blockIdx.x * blockDim.x + threadIdx.x;
    if (idx >= B_ * D_) return;
    int b = idx / D_;
    int d = idx - b * D_;
    float v = b_out[d];
    #pragma unroll
    for (int s = 0; s < 8; s++) v += g_proj[s][idx];
    out[b * (T_ * D_) + t * D_ + d] = v;
    __nv_bfloat16 hi = __float2bfloat16(v);
    g_xd_hi[b * XP + d] = hi;
    g_xd_lo[b * XP + d] = __float2bfloat16(v - __bfloat162float(hi));
}

// ---------------- host orchestration ----------------------------------------
extern "C" void kernel_launch(void* const* d_in, const int* in_sizes, int n_in,
                              void* d_out, int out_size)
{
    (void)in_sizes; (void)n_in; (void)out_size;
    const float* src   = (const float*)d_in[0];
    const float* W_ih  = (const float*)d_in[2];
    const float* W_hh  = (const float*)d_in[3];
    const float* b_ih  = (const float*)d_in[4];
    const float* b_hh  = (const float*)d_in[5];
    const float* W_out = (const float*)d_in[6];
    const float* b_out = (const float*)d_in[7];
    float* out = (float*)d_out;

    cudaFuncSetAttribute(lstm_step_mma,
                         cudaFuncAttributeMaxDynamicSharedMemorySize, SMEM_DYN);

    prep_weights<<<(G_ * KP) / 256, 256>>>(W_ih, W_hh, b_ih, b_hh);
    prep_xe<<<(S_ * B_ * XP) / 256, 256>>>(src);
    init_state<<<(B_ * H_) / 256, 256>>>();

    dim3 gg(G_ / 64, B_ / 128);   // (64, 2) = 128 CTAs
    dim3 pg(4, B_ / 128, 8);
    int cur = 0;

    // Encoder
    for (int t = 0; t < S_; t++) {
        lstm_step_mma<<<gg, 256, SMEM_DYN>>>(cur, 0, t * B_ * XP);
        cur ^= 1;
    }
    // Decoder
    for (int t = 0; t < T_; t++) {
        if (t == 0)
            lstm_step_mma<<<gg, 256, SMEM_DYN>>>(cur, 0, (S_ - 1) * B_ * XP);
        else
            lstm_step_mma<<<gg, 256, SMEM_DYN>>>(cur, 1, 0);
        cur ^= 1;
        proj_gemm<<<pg, 256>>>(W_out);
        proj_reduce<<<(B_ * D_ + 255) / 256, 256>>>(b_out, out, t);
    }
}

// round 7
// speedup vs baseline: 2.3844x; 1.0355x over previous
#include <cuda_runtime.h>
#include <cuda_bf16.h>
#include <math.h>
#include <stdint.h>

#define B_ 256
#define S_ 120
#define T_ 24
#define D_ 216
#define H_ 1024
#define G_ 4096           // 4*H
#define KP 1280           // padded K (1024 h + 216 x + 40 zero)
#define XP 256            // padded x row width
#define BK 32
#define NCH (KP / BK)     // 40
#define NSTAGE 4
// per-stage smem: A 2 splits x 64 rows x 80B + B 2 splits x 64 rows x 80B
#define A_PITCH 80
#define ASPLIT_BYTES (64 * A_PITCH)    // 5120
#define BSPLIT_BYTES (64 * A_PITCH)    // 5120
#define STAGE_BYTES (2 * ASPLIT_BYTES + 2 * BSPLIT_BYTES)  // 20480
#define SMEM_DYN (NSTAGE * STAGE_BYTES)                    // 81920

// ---------------- device globals (no allocations allowed) --------------------
__device__ __align__(16) __nv_bfloat16 g_Wp_hi[G_ * KP];      // permuted, split
__device__ __align__(16) __nv_bfloat16 g_Wp_lo[G_ * KP];
__device__ __align__(16) __nv_bfloat16 g_xe_hi[S_ * B_ * XP]; // encoder x splits
__device__ __align__(16) __nv_bfloat16 g_xe_lo[S_ * B_ * XP];
__device__ __align__(16) __nv_bfloat16 g_xd_hi[B_ * XP];      // decoder x splits
__device__ __align__(16) __nv_bfloat16 g_xd_lo[B_ * XP];
__device__ __align__(16) __nv_bfloat16 g_ah_hi[2][B_ * H_];   // h splits, ping-pong
__device__ __align__(16) __nv_bfloat16 g_ah_lo[2][B_ * H_];
__device__ float g_hf[B_ * H_];       // fp32 h (projection input)
__device__ float g_c[B_ * H_];        // cell state
__device__ float g_bp[G_];            // permuted combined bias
__device__ float g_proj[8][B_ * D_];  // split-K projection partials

__device__ __forceinline__ float sigf(float v) { return 1.f / (1.f + expf(-v)); }

// ---------------- PTX helpers (baseline sm_80+ only) -------------------------
__device__ __forceinline__ uint32_t smem_u32(const void* p) {
    uint32_t a;
    asm("{ .reg .u64 t; cvta.to.shared.u64 t, %1; cvt.u32.u64 %0, t; }"
        : "=r"(a) : "l"(p));
    return a;
}
#define CP_ASYNC16(dst, src) \
    asm volatile("cp.async.ca.shared.global [%0], [%1], 16;" :: "r"(dst), "l"(src))
#define CP_COMMIT() asm volatile("cp.async.commit_group;" ::: "memory")
#define CP_WAIT2()  asm volatile("cp.async.wait_group 2;" ::: "memory")
#define CP_WAIT0()  asm volatile("cp.async.wait_group 0;" ::: "memory")

#define LDSM_X4(r0, r1, r2, r3, a) \
    asm volatile("ldmatrix.sync.aligned.m8n8.x4.shared.b16 {%0,%1,%2,%3}, [%4];" \
                 : "=r"(r0), "=r"(r1), "=r"(r2), "=r"(r3) : "r"(a))

#define MMA16816(d, a, b) \
    asm volatile("mma.sync.aligned.m16n8k16.row.col.f32.bf16.bf16.f32 " \
                 "{%0,%1,%2,%3},{%4,%5,%6,%7},{%8,%9},{%0,%1,%2,%3};" \
                 : "+f"((d)[0]), "+f"((d)[1]), "+f"((d)[2]), "+f"((d)[3]) \
                 : "r"((a)[0]), "r"((a)[1]), "r"((a)[2]), "r"((a)[3]), \
                   "r"((b)[0]), "r"((b)[1]))

// ---------------- prep kernels ----------------------------------------------
// Permutation: permuted col p -> bn=p>>6, c=p&63, u=c>>2, q=c&3, unit j=bn*16+u,
// original weight row = q*H_ + j. A CTA's 64 cols = 16 units x 4 gates.
__global__ void prep_weights(const float* __restrict__ W_ih,
                             const float* __restrict__ W_hh,
                             const float* __restrict__ b_ih,
                             const float* __restrict__ b_hh)
{
    int idx = blockIdx.x * blockDim.x + threadIdx.x;  // G_*KP threads
    int p = idx / KP, k = idx - p * KP;
    int bn = p >> 6, c = p & 63, u = c >> 2, q = c & 3;
    int j = bn * 16 + u;
    int orig = q * H_ + j;
    float w = 0.f;
    if (k < H_) w = W_hh[orig * H_ + k];
    else if (k < H_ + D_) w = W_ih[orig * D_ + (k - H_)];
    __nv_bfloat16 hi = __float2bfloat16(w);
    g_Wp_hi[idx] = hi;
    g_Wp_lo[idx] = __float2bfloat16(w - __bfloat162float(hi));
    if (k == 0) g_bp[p] = b_ih[orig] + b_hh[orig];
}

__global__ void prep_xe(const float* __restrict__ src)
{
    int idx = blockIdx.x * blockDim.x + threadIdx.x;  // S_*B_*XP threads
    int t = idx >> 16;            // B_*XP = 65536
    int r = idx & 65535;
    int b = r >> 8, kk = r & 255;
    float v = (kk < D_) ? src[(b * S_ + t) * D_ + kk] : 0.f;
    __nv_bfloat16 hi = __float2bfloat16(v);
    g_xe_hi[idx] = hi;
    g_xe_lo[idx] = __float2bfloat16(v - __bfloat162float(hi));
}

__global__ void init_state()
{
    int idx = blockIdx.x * blockDim.x + threadIdx.x;
    if (idx < B_ * H_) {
        g_c[idx] = 0.f;
        g_ah_hi[0][idx] = __float2bfloat16(0.f);
        g_ah_lo[0][idx] = __float2bfloat16(0.f);
    }
    if (idx < B_ * XP) {
        g_xd_hi[idx] = __float2bfloat16(0.f);
        g_xd_lo[idx] = __float2bfloat16(0.f);
    }
}

// ---------------- fused LSTM step: HMMA split-bf16 GEMM + cell ---------------
// grid (64, 4): blockIdx.x = N tile (64 permuted cols = 16 units),
//               blockIdx.y = M tile (64 batch rows). 256 threads = 8 warps 4x2.
// 2 CTAs per SM (launch_bounds), 4-stage cp.async pipeline, 1 sync per chunk.
__global__ void __launch_bounds__(256, 2)
lstm_step_mma(int hbuf, int xsel, int xoff)
{
    extern __shared__ __align__(128) char smem[];
    const uint32_t sb = smem_u32(smem);
    const int tid = threadIdx.x;
    const int wid = tid >> 5;
    const int lane = tid & 31;
    const int bn = blockIdx.x;
    const int m0 = blockIdx.y << 6;
    const int n0 = bn << 6;

    const __nv_bfloat16* __restrict__ ah_hi = g_ah_hi[hbuf];
    const __nv_bfloat16* __restrict__ ah_lo = g_ah_lo[hbuf];
    const __nv_bfloat16* __restrict__ x_hi = xsel ? g_xd_hi : (g_xe_hi + xoff);
    const __nv_bfloat16* __restrict__ x_lo = xsel ? g_xd_lo : (g_xe_lo + xoff);
    const __nv_bfloat16* __restrict__ wp_hi = g_Wp_hi;
    const __nv_bfloat16* __restrict__ wp_lo = g_Wp_lo;

    // stage loader: A 512 x 16B + B 512 x 16B per stage -> 4 cp.async per thread
    auto load_stage = [&](int ch, int slot) {
        uint32_t s = sb + slot * STAGE_BYTES;
        #pragma unroll
        for (int i = 0; i < 2; i++) {
            int idx = i * 256 + tid;
            int row = idx >> 3, rem = idx & 7;
            int split = rem >> 2, c4 = rem & 3;
            const __nv_bfloat16* g;
            if (ch < 32)
                g = (split ? ah_lo : ah_hi) + (size_t)(m0 + row) * H_ + ch * BK + c4 * 8;
            else
                g = (split ? x_lo : x_hi) + (size_t)(m0 + row) * XP + (ch - 32) * BK + c4 * 8;
            CP_ASYNC16(s + split * ASPLIT_BYTES + row * A_PITCH + c4 * 16, g);
        }
        #pragma unroll
        for (int i = 0; i < 2; i++) {
            int idx = i * 256 + tid;
            int row = idx >> 3, rem = idx & 7;
            int split = rem >> 2, c4 = rem & 3;
            const __nv_bfloat16* g =
                (split ? wp_lo : wp_hi) + (size_t)(n0 + row) * KP + ch * BK + c4 * 8;
            CP_ASYNC16(s + 2 * ASPLIT_BYTES + split * BSPLIT_BYTES
                         + row * A_PITCH + c4 * 16, g);
        }
    };

    const int warpM = wid & 3;    // 0..3 -> rows warpM*16
    const int warpN = wid >> 2;   // 0..1 -> cols warpN*32

    // split accumulators: accA gets hi*hi (1-deep chain), accB gets both
    // cross terms (2-deep). Summed in the epilogue.
    float accA[4][4], accB[4][4];
    #pragma unroll
    for (int j = 0; j < 4; j++)
        #pragma unroll
        for (int q = 0; q < 4; q++) { accA[j][q] = 0.f; accB[j][q] = 0.f; }

    // ldmatrix lane-address components (constant per thread)
    const int tsel = lane >> 3;          // tile index 0..3
    // A x4 tiles: t0 m-lo k-lo, t1 m-hi k-lo, t2 m-lo k-hi, t3 m-hi k-hi
    const int aRow = (tsel & 1) * 8 + (lane & 7);
    const int aKof = (tsel >> 1) * 16;   // bytes
    // B x4 tiles: t0 n-lo k-lo, t1 n-lo k-hi, t2 n-hi k-lo, t3 n-hi k-hi
    const int bRow = (tsel >> 1) * 8 + (lane & 7);
    const int bKof = (tsel & 1) * 16;    // bytes

    load_stage(0, 0); CP_COMMIT();
    load_stage(1, 1); CP_COMMIT();
    load_stage(2, 2); CP_COMMIT();

    #pragma unroll 1
    for (int ch = 0; ch < NCH; ch++) {
        CP_WAIT2();                 // stage ch resident
        __syncthreads();
        if (ch + 3 < NCH) load_stage(ch + 3, (ch + 3) & 3);
        CP_COMMIT();

        uint32_t s = sb + (ch & 3) * STAGE_BYTES;
        #pragma unroll
        for (int kh = 0; kh < 2; kh++) {
            uint32_t a_hi[4], a_lo[4];
            {
                uint32_t ra = s + (warpM * 16 + aRow) * A_PITCH + kh * 32 + aKof;
                LDSM_X4(a_hi[0], a_hi[1], a_hi[2], a_hi[3], ra);
                LDSM_X4(a_lo[0], a_lo[1], a_lo[2], a_lo[3], ra + ASPLIT_BYTES);
            }
            uint32_t b_hi[4][2], b_lo[4][2];
            #pragma unroll
            for (int gq = 0; gq < 2; gq++) {
                uint32_t rb = s + 2 * ASPLIT_BYTES
                                + (warpN * 32 + gq * 16 + bRow) * A_PITCH
                                + kh * 32 + bKof;
                uint32_t r0, r1, r2, r3;
                LDSM_X4(r0, r1, r2, r3, rb);
                b_hi[gq * 2 + 0][0] = r0; b_hi[gq * 2 + 0][1] = r1;
                b_hi[gq * 2 + 1][0] = r2; b_hi[gq * 2 + 1][1] = r3;
                LDSM_X4(r0, r1, r2, r3, rb + BSPLIT_BYTES);
                b_lo[gq * 2 + 0][0] = r0; b_lo[gq * 2 + 0][1] = r1;
                b_lo[gq * 2 + 1][0] = r2; b_lo[gq * 2 + 1][1] = r3;
            }
            #pragma unroll
            for (int ni = 0; ni < 4; ni++) {
                MMA16816(accA[ni], a_hi, b_hi[ni]);
                MMA16816(accB[ni], a_hi, b_lo[ni]);
                MMA16816(accB[ni], a_lo, b_hi[ni]);
            }
        }
    }
    CP_WAIT0();
    __syncthreads();

    // ---- epilogue: stage gates through smem, fused LSTM cell ----
    float* gbuf = (float*)smem;           // [64][68] f32 = 17.4KB (reuses stages)
    const int GP = 68;
    #pragma unroll
    for (int ni = 0; ni < 4; ni++) {
        int r0 = warpM * 16 + (lane >> 2);
        int c0 = warpN * 32 + ni * 8 + 2 * (lane & 3);
        gbuf[r0 * GP + c0]           = accA[ni][0] + accB[ni][0];
        gbuf[r0 * GP + c0 + 1]       = accA[ni][1] + accB[ni][1];
        gbuf[(r0 + 8) * GP + c0]     = accA[ni][2] + accB[ni][2];
        gbuf[(r0 + 8) * GP + c0 + 1] = accA[ni][3] + accB[ni][3];
    }
    __syncthreads();

    {
        const int u = tid & 15;           // local unit 0..15
        const int rg = tid >> 4;          // row group 0..15 (4 rows each)
        const int j = bn * 16 + u;        // global hidden unit
        const float bi = g_bp[n0 + u * 4 + 0];
        const float bf = g_bp[n0 + u * 4 + 1];
        const float bg = g_bp[n0 + u * 4 + 2];
        const float bo = g_bp[n0 + u * 4 + 3];
        __nv_bfloat16* __restrict__ oh = g_ah_hi[1 - hbuf];
        __nv_bfloat16* __restrict__ ol = g_ah_lo[1 - hbuf];
        #pragma unroll
        for (int rr = 0; rr < 4; rr++) {
            int r = rg * 4 + rr;
            const float* gr = &gbuf[r * GP + u * 4];
            float gi = gr[0] + bi;
            float gf = gr[1] + bf;
            float gg = gr[2] + bg;
            float go = gr[3] + bo;
            size_t idx = (size_t)(m0 + r) * H_ + j;
            float cn = sigf(gf) * g_c[idx] + sigf(gi) * tanhf(gg);
            g_c[idx] = cn;
            float hn = sigf(go) * tanhf(cn);
            g_hf[idx] = hn;
            __nv_bfloat16 hh = __float2bfloat16(hn);
            oh[idx] = hh;
            ol[idx] = __float2bfloat16(hn - __bfloat162float(hh));
        }
    }
}

// ---------------- projection GEMM (fp32, split-K=8; reads g_hf) --------------
__global__ void __launch_bounds__(256, 2)
proj_gemm(const float* __restrict__ Wout)
{
    __shared__ float As[2][8][132];
    __shared__ float Bs[2][8][68];

    const float* __restrict__ h = g_hf;
    int tid = threadIdx.x;
    int n0 = blockIdx.x * 64;
    int m0 = blockIdx.y * 128;
    int ks = blockIdx.z;
    int kbase = ks * 128;

    int lmA = tid >> 1, lkA = (tid & 1) * 4;
    int lmB = tid >> 2, lkB = (tid & 3) * 2;
    int ty = tid >> 4, tx = tid & 15;

    float acc[8][4];
    #pragma unroll
    for (int i = 0; i < 8; i++)
        #pragma unroll
        for (int j = 0; j < 4; j++) acc[i][j] = 0.f;

    float4 aR; float2 bR;
    int dB = n0 + lmB;

    aR = *(const float4*)&h[(m0 + lmA) * H_ + kbase + lkA];
    bR = (dB < D_) ? *(const float2*)&Wout[dB * H_ + kbase + lkB] : make_float2(0.f, 0.f);
    As[0][lkA + 0][lmA] = aR.x; As[0][lkA + 1][lmA] = aR.y;
    As[0][lkA + 2][lmA] = aR.z; As[0][lkA + 3][lmA] = aR.w;
    Bs[0][lkB + 0][lmB] = bR.x; Bs[0][lkB + 1][lmB] = bR.y;
    __syncthreads();

    const int NC = 16;
    for (int ch = 1; ch <= NC; ch++) {
        if (ch < NC) {
            int k0 = kbase + ch * 8;
            aR = *(const float4*)&h[(m0 + lmA) * H_ + k0 + lkA];
            bR = (dB < D_) ? *(const float2*)&Wout[dB * H_ + k0 + lkB] : make_float2(0.f, 0.f);
        }
        int cb = (ch - 1) & 1;
        #pragma unroll
        for (int k = 0; k < 8; k++) {
            float4 a0 = *(const float4*)&As[cb][k][ty * 8];
            float4 a1 = *(const float4*)&As[cb][k][ty * 8 + 4];
            float4 bb = *(const float4*)&Bs[cb][k][tx * 4];
            float av[8] = {a0.x, a0.y, a0.z, a0.w, a1.x, a1.y, a1.z, a1.w};
            float bv[4] = {bb.x, bb.y, bb.z, bb.w};
            #pragma unroll
            for (int i = 0; i < 8; i++)
                #pragma unroll
                for (int j = 0; j < 4; j++)
                    acc[i][j] += av[i] * bv[j];
        }
        if (ch < NC) {
            int sbuf = ch & 1;
            As[sbuf][lkA + 0][lmA] = aR.x; As[sbuf][lkA + 1][lmA] = aR.y;
            As[sbuf][lkA + 2][lmA] = aR.z; As[sbuf][lkA + 3][lmA] = aR.w;
            Bs[sbuf][lkB + 0][lmB] = bR.x; Bs[sbuf][lkB + 1][lmB] = bR.y;
        }
        __syncthreads();
    }

    #pragma unroll
    for (int i = 0; i < 8; i++)
        #pragma unroll
        for (int j = 0; j < 4; j++) {
            int col = n0 + tx * 4 + j;
            if (col < D_)
                g_proj[ks][(m0 + ty * 8 + i) * D_ + col] = acc[i][j];
        }
}

// ---------------- projection reduce: output + decoder-feedback split ---------
__global__ void proj_reduce(const float* __restrict__ b_out,
                            float* __restrict__ out, int t)
{
    int idx = blockIdx.x * blockDim.x + threadIdx.x;
    if (idx >= B_ * D_) return;
    int b = idx / D_;
    int d = idx - b * D_;
    float v = b_out[d];
    #pragma unroll
    for (int s = 0; s < 8; s++) v += g_proj[s][idx];
    out[b * (T_ * D_) + t * D_ + d] = v;
    __nv_bfloat16 hi = __float2bfloat16(v);
    g_xd_hi[b * XP + d] = hi;
    g_xd_lo[b * XP + d] = __float2bfloat16(v - __bfloat162float(hi));
}

// ---------------- host orchestration ----------------------------------------
extern "C" void kernel_launch(void* const* d_in, const int* in_sizes, int n_in,
                              void* d_out, int out_size)
{
    (void)in_sizes; (void)n_in; (void)out_size;
    const float* src   = (const float*)d_in[0];
    const float* W_ih  = (const float*)d_in[2];
    const float* W_hh  = (const float*)d_in[3];
    const float* b_ih  = (const float*)d_in[4];
    const float* b_hh  = (const float*)d_in[5];
    const float* W_out = (const float*)d_in[6];
    const float* b_out = (const float*)d_in[7];
    float* out = (float*)d_out;

    cudaFuncSetAttribute(lstm_step_mma,
                         cudaFuncAttributeMaxDynamicSharedMemorySize, SMEM_DYN);

    prep_weights<<<(G_ * KP) / 256, 256>>>(W_ih, W_hh, b_ih, b_hh);
    prep_xe<<<(S_ * B_ * XP) / 256, 256>>>(src);
    init_state<<<(B_ * H_) / 256, 256>>>();

    dim3 gg(G_ / 64, B_ / 64);    // (64, 4) = 256 CTAs, 2 per SM
    dim3 pg(4, B_ / 128, 8);
    int cur = 0;

    // Encoder
    for (int t = 0; t < S_; t++) {
        lstm_step_mma<<<gg, 256, SMEM_DYN>>>(cur, 0, t * B_ * XP);
        cur ^= 1;
    }
    // Decoder
    for (int t = 0; t < T_; t++) {
        if (t == 0)
            lstm_step_mma<<<gg, 256, SMEM_DYN>>>(cur, 0, (S_ - 1) * B_ * XP);
        else
            lstm_step_mma<<<gg, 256, SMEM_DYN>>>(cur, 1, 0);
        cur ^= 1;
        proj_gemm<<<pg, 256>>>(W_out);
        proj_reduce<<<(B_ * D_ + 255) / 256, 256>>>(b_out, out, t);
    }
}